// round 2
// baseline (speedup 1.0000x reference)
#include <cuda_runtime.h>

// Problem constants
#define BATCH 4
#define SEQ   2048
#define CDIM  1024
#define HEADS 16
#define HDIM  64
#define BT    (BATCH * SEQ)       // 8192 rows
#define C3    (3 * CDIM)          // 3072

// Scratch in device globals (no dynamic allocation allowed)
__device__ float g_qkv[(size_t)BT * C3];   // [B*T, 3C]
__device__ float g_y[(size_t)BT * CDIM];   // [B*T, C] attention output

// ---------------------------------------------------------------------------
// Tiled SGEMM with bias: C[M,N] = A[M,K] @ B[K,N] + bias[N]
// 64x64 block tile, 16-deep K tile, 256 threads, 4x4 per-thread micro-tile.
// M, N, K all divisible by tile sizes for our shapes.
// ---------------------------------------------------------------------------
__global__ __launch_bounds__(256) void sgemm_bias(
    const float* __restrict__ A, const float* __restrict__ B,
    const float* __restrict__ bias, float* __restrict__ Cout,
    int M, int N, int K)
{
    __shared__ float As[16][64];
    __shared__ float Bs[16][64];

    const int tx = threadIdx.x & 15;
    const int ty = threadIdx.x >> 4;
    const int m0 = blockIdx.y * 64;
    const int n0 = blockIdx.x * 64;

    float acc[4][4] = {};

    for (int k0 = 0; k0 < K; k0 += 16) {
        // Load A tile (64 rows x 16 k) : 1024 elems, 4 per thread
        #pragma unroll
        for (int l = 0; l < 4; l++) {
            int idx = threadIdx.x + l * 256;
            int i  = idx >> 4;
            int kk = idx & 15;
            As[kk][i] = A[(size_t)(m0 + i) * K + k0 + kk];
        }
        // Load B tile (16 k x 64 cols) : 1024 elems, coalesced over cols
        #pragma unroll
        for (int l = 0; l < 4; l++) {
            int idx = threadIdx.x + l * 256;
            int kk = idx >> 6;
            int j  = idx & 63;
            Bs[kk][j] = B[(size_t)(k0 + kk) * N + n0 + j];
        }
        __syncthreads();

        #pragma unroll
        for (int kk = 0; kk < 16; kk++) {
            float a[4], b[4];
            #pragma unroll
            for (int i = 0; i < 4; i++) a[i] = As[kk][ty * 4 + i];
            #pragma unroll
            for (int j = 0; j < 4; j++) b[j] = Bs[kk][tx * 4 + j];
            #pragma unroll
            for (int i = 0; i < 4; i++)
                #pragma unroll
                for (int j = 0; j < 4; j++)
                    acc[i][j] += a[i] * b[j];
        }
        __syncthreads();
    }

    #pragma unroll
    for (int i = 0; i < 4; i++) {
        int r = m0 + ty * 4 + i;
        #pragma unroll
        for (int j = 0; j < 4; j++) {
            int c = n0 + tx * 4 + j;
            Cout[(size_t)r * N + c] = acc[i][j] + bias[c];
        }
    }
}

// ---------------------------------------------------------------------------
// Flash attention (causal), fp32. One block = one (batch, head, 64-row Q tile).
// 64 threads; thread t owns query row (qt*64 + t). K/V tiles of 32 rows in
// shared; q vector and output accumulator in registers; online softmax.
// ---------------------------------------------------------------------------
__global__ __launch_bounds__(64) void attn_kernel()
{
    __shared__ float qs[64][64];   // Q tile (staging for coalesced load)
    __shared__ float ks[32][64];   // K tile
    __shared__ float vs[32][64];   // V tile
    __shared__ float ss[64][33];   // per-thread score row (padded: conflict-free)

    const int qt  = blockIdx.x;
    const int h   = blockIdx.y;
    const int b   = blockIdx.z;
    const int tid = threadIdx.x;

    const float* qkv = g_qkv + (size_t)b * SEQ * C3;
    const int qg = qt * 64 + tid;              // global query index of this thread

    // Coalesced Q-tile load: per iteration the 64 threads load one 64-float row
    for (int r = 0; r < 64; r++) {
        qs[r][tid] = qkv[(size_t)(qt * 64 + r) * C3 + h * HDIM + tid];
    }
    __syncthreads();

    float qreg[64];
    #pragma unroll
    for (int d = 0; d < 64; d++) qreg[d] = qs[tid][d];

    float acc[64];
    #pragma unroll
    for (int d = 0; d < 64; d++) acc[d] = 0.f;
    float m = -1e30f;
    float l = 0.f;
    const float scale = 0.125f;  // 1/sqrt(64)

    const int kv_end = qt * 64 + 64;   // exclusive; causal mask handles the rest
    for (int j0 = 0; j0 < kv_end; j0 += 32) {
        __syncthreads();   // protect ks/vs from previous iteration
        // Load K and V tiles (coalesced: thread = column)
        for (int r = 0; r < 32; r++) {
            ks[r][tid] = qkv[(size_t)(j0 + r) * C3 + CDIM     + h * HDIM + tid];
            vs[r][tid] = qkv[(size_t)(j0 + r) * C3 + 2 * CDIM + h * HDIM + tid];
        }
        __syncthreads();

        // Scores + tile max
        float mt = m;
        for (int jj = 0; jj < 32; jj++) {
            float dot = 0.f;
            #pragma unroll
            for (int d = 0; d < 64; d++) dot += qreg[d] * ks[jj][d];
            dot *= scale;
            if (j0 + jj > qg) dot = -1e30f;   // causal mask
            ss[tid][jj] = dot;
            mt = fmaxf(mt, dot);
        }

        // Rescale running state
        float corr = __expf(m - mt);
        l *= corr;
        #pragma unroll
        for (int d = 0; d < 64; d++) acc[d] *= corr;

        // Accumulate P @ V
        for (int jj = 0; jj < 32; jj++) {
            float p = __expf(ss[tid][jj] - mt);
            l += p;
            #pragma unroll
            for (int d = 0; d < 64; d++) acc[d] += p * vs[jj][d];
        }
        m = mt;
    }

    const float inv = 1.f / l;
    float* yrow = g_y + (size_t)(b * SEQ + qg) * CDIM + h * HDIM;
    #pragma unroll
    for (int d = 0; d < 64; d++) yrow[d] = acc[d] * inv;
}

// ---------------------------------------------------------------------------
// Launch
// ---------------------------------------------------------------------------
extern "C" void kernel_launch(void* const* d_in, const int* in_sizes, int n_in,
                              void* d_out, int out_size)
{
    const float* x      = (const float*)d_in[0];  // [B,T,C]
    const float* W_attn = (const float*)d_in[1];  // [C,3C]
    const float* b_attn = (const float*)d_in[2];  // [3C]
    const float* W_proj = (const float*)d_in[3];  // [C,C]
    const float* b_proj = (const float*)d_in[4];  // [C]
    float* out = (float*)d_out;                   // [B,T,C]

    float* qkv = nullptr;
    float* y   = nullptr;
    cudaGetSymbolAddress((void**)&qkv, g_qkv);
    cudaGetSymbolAddress((void**)&y, g_y);

    // 1) QKV projection: [8192,1024] @ [1024,3072] + b
    {
        dim3 grid(C3 / 64, BT / 64);
        sgemm_bias<<<grid, 256>>>(x, W_attn, b_attn, qkv, BT, C3, CDIM);
    }
    // 2) Causal flash attention
    {
        dim3 grid(SEQ / 64, HEADS, BATCH);
        attn_kernel<<<grid, 64>>>();
    }
    // 3) Output projection: [8192,1024] @ [1024,1024] + b
    {
        dim3 grid(CDIM / 64, BT / 64);
        sgemm_bias<<<grid, 256>>>(y, W_proj, b_proj, out, BT, CDIM, CDIM);
    }
}

// round 5
// speedup vs baseline: 3.9373x; 3.9373x over previous
#include <cuda_runtime.h>

// Problem constants
#define BATCH 4
#define SEQ   2048
#define CDIM  1024
#define HEADS 16
#define HDIM  64
#define BT    (BATCH * SEQ)       // 8192 rows
#define C3    (3 * CDIM)          // 3072

// Scratch in device globals (no dynamic allocation allowed)
__device__ float g_qkv[(size_t)BT * C3];   // [B*T, 3C]
__device__ float g_y[(size_t)BT * CDIM];   // [B*T, C] attention output

// ---------------------------------------------------------------------------
// Helpers: tf32 convert (round-to-nearest) and m16n8k8 tf32 MMA
// ---------------------------------------------------------------------------
__device__ __forceinline__ unsigned f2tf(float f) {
    unsigned r;
    asm("cvt.rna.tf32.f32 %0, %1;" : "=r"(r) : "f"(f));
    return r;
}

__device__ __forceinline__ void mma8(float* c, const unsigned* a, const unsigned* b) {
    asm volatile(
        "mma.sync.aligned.m16n8k8.row.col.f32.tf32.tf32.f32 "
        "{%0,%1,%2,%3}, {%4,%5,%6,%7}, {%8,%9}, {%0,%1,%2,%3};"
        : "+f"(c[0]), "+f"(c[1]), "+f"(c[2]), "+f"(c[3])
        : "r"(a[0]), "r"(a[1]), "r"(a[2]), "r"(a[3]), "r"(b[0]), "r"(b[1]));
}

// ---------------------------------------------------------------------------
// TF32 tensor-core GEMM with bias: C[M,N] = A[M,K] @ B[K,N] + bias[N]
// Block tile 128x128, K tile 32. 256 threads = 8 warps (2x4), warp tile 64x32.
// ---------------------------------------------------------------------------
#define GS_A 36   // As row stride (floats): 36 % 32 == 4 -> frag loads conflict-free
#define GS_B 33   // Bs row stride: STS conflict-free, frag loads mildly conflicted

__global__ __launch_bounds__(256) void gemm_tf32(
    const float* __restrict__ A, const float* __restrict__ B,
    const float* __restrict__ bias, float* __restrict__ C,
    int M, int N, int K)
{
    __shared__ unsigned As[128 * GS_A];   // [m][k], tf32
    __shared__ unsigned Bs[128 * GS_B];   // [n][k] (transposed), tf32

    const int tid  = threadIdx.x;
    const int lane = tid & 31;
    const int warp = tid >> 5;
    const int g    = lane >> 2;     // 0..7
    const int tg   = lane & 3;      // 0..3
    const int wm   = (warp >> 2) * 64;  // warp M offset in block
    const int wn   = (warp & 3) * 32;   // warp N offset in block
    const int m0   = blockIdx.y * 128;
    const int n0   = blockIdx.x * 128;

    float acc[4][4][4] = {};  // [mtile][ntile][frag]

    // global-load register double buffer
    float pa[4][4];
    float pb[16];
    const int ar  = tid >> 3;        // 0..31 (A row within 32-row group)
    const int ac  = (tid & 7) * 4;   // A col (float4)
    const int bj  = tid & 127;       // B col
    const int bk2 = tid >> 7;        // 0/1

    // initial prefetch (k0 = 0)
    #pragma unroll
    for (int it = 0; it < 4; it++) {
        const float4 v = *(const float4*)&A[(size_t)(m0 + it * 32 + ar) * K + ac];
        pa[it][0] = v.x; pa[it][1] = v.y; pa[it][2] = v.z; pa[it][3] = v.w;
    }
    #pragma unroll
    for (int it = 0; it < 16; it++)
        pb[it] = B[(size_t)(it * 2 + bk2) * N + n0 + bj];

    for (int k0 = 0; k0 < K; k0 += 32) {
        // commit prefetched tile to smem (tf32-rounded)
        #pragma unroll
        for (int it = 0; it < 4; it++)
            #pragma unroll
            for (int c = 0; c < 4; c++)
                As[(it * 32 + ar) * GS_A + ac + c] = f2tf(pa[it][c]);
        #pragma unroll
        for (int it = 0; it < 16; it++)
            Bs[bj * GS_B + it * 2 + bk2] = f2tf(pb[it]);
        __syncthreads();

        // prefetch next tile (overlaps with compute below)
        if (k0 + 32 < K) {
            const int kn = k0 + 32;
            #pragma unroll
            for (int it = 0; it < 4; it++) {
                const float4 v = *(const float4*)&A[(size_t)(m0 + it * 32 + ar) * K + kn + ac];
                pa[it][0] = v.x; pa[it][1] = v.y; pa[it][2] = v.z; pa[it][3] = v.w;
            }
            #pragma unroll
            for (int it = 0; it < 16; it++)
                pb[it] = B[(size_t)(kn + it * 2 + bk2) * N + n0 + bj];
        }

        // compute: 4 k-steps of k=8
        #pragma unroll
        for (int ks = 0; ks < 4; ks++) {
            unsigned af[4][4], bf[4][2];
            #pragma unroll
            for (int mt = 0; mt < 4; mt++) {
                const unsigned* p = &As[(wm + mt * 16 + g) * GS_A + ks * 8 + tg];
                af[mt][0] = p[0];
                af[mt][1] = p[8 * GS_A];
                af[mt][2] = p[4];
                af[mt][3] = p[8 * GS_A + 4];
            }
            #pragma unroll
            for (int nt = 0; nt < 4; nt++) {
                const unsigned* p = &Bs[(wn + nt * 8 + g) * GS_B + ks * 8 + tg];
                bf[nt][0] = p[0];
                bf[nt][1] = p[4];
            }
            #pragma unroll
            for (int mt = 0; mt < 4; mt++)
                #pragma unroll
                for (int nt = 0; nt < 4; nt++)
                    mma8(acc[mt][nt], af[mt], bf[nt]);
        }
        __syncthreads();
    }

    // epilogue: bias + store (float2 per fragment row)
    #pragma unroll
    for (int mt = 0; mt < 4; mt++) {
        const int r0 = m0 + wm + mt * 16 + g;
        #pragma unroll
        for (int nt = 0; nt < 4; nt++) {
            const int c0 = n0 + wn + nt * 8 + tg * 2;
            const float b0v = bias[c0], b1v = bias[c0 + 1];
            *(float2*)&C[(size_t)r0 * N + c0] =
                make_float2(acc[mt][nt][0] + b0v, acc[mt][nt][1] + b1v);
            *(float2*)&C[(size_t)(r0 + 8) * N + c0] =
                make_float2(acc[mt][nt][2] + b0v, acc[mt][nt][3] + b1v);
        }
    }
}

// ---------------------------------------------------------------------------
// Flash attention (causal), tf32 tensor cores.
// Block = (qtile of 64 rows, head, batch). 128 threads = 4 warps.
// Warp w owns Q rows [w*16, w*16+16) of the tile.
// ---------------------------------------------------------------------------
#define AS 68   // smem row stride (floats): 68 % 32 == 4 -> frag loads conflict-free

__global__ __launch_bounds__(128) void attn_tf32()
{
    extern __shared__ unsigned smem[];
    unsigned* sq  = smem;              // [64][AS]  Q (scaled, tf32)
    unsigned* sk  = sq  + 64 * AS;     // [64][AS]  K
    unsigned* svt = sk  + 64 * AS;     // [64][AS]  V^T (svt[d][j])
    unsigned* sp  = svt + 64 * AS;     // [64][AS]  P

    const int tid  = threadIdx.x;
    const int lane = tid & 31;
    const int warp = tid >> 5;         // 0..3
    const int g    = lane >> 2;        // 0..7
    const int tg   = lane & 3;         // 0..3

    const int qt = blockIdx.x;
    const int h  = blockIdx.y;
    const int b  = blockIdx.z;
    const float* qkv = g_qkv + (size_t)b * SEQ * C3;

    const int d  = tid & 63;
    const int rh = tid >> 6;           // 0/1

    // Load Q tile (pre-scaled by 1/sqrt(D) = 0.125, exact power of 2)
    for (int it = 0; it < 32; it++) {
        const int r = it * 2 + rh;
        sq[r * AS + d] = f2tf(qkv[(size_t)(qt * 64 + r) * C3 + h * HDIM + d] * 0.125f);
    }

    float o[8][4] = {};                       // O fragments: 16 rows x 64 cols per warp
    float mrun[2] = {-1e30f, -1e30f};
    float lrun[2] = {0.f, 0.f};
    const int rowA = qt * 64 + warp * 16 + g; // global seq row for c0/c1 (c2/c3: +8)

    for (int j0 = 0; j0 <= qt * 64; j0 += 64) {
        __syncthreads();   // protect sk/svt (and sq on first iter ordering)
        // Load K tile and V tile (V transposed into svt[d][j])
        for (int it = 0; it < 32; it++) {
            const int r = it * 2 + rh;
            sk[r * AS + d]  = f2tf(qkv[(size_t)(j0 + r) * C3 + CDIM     + h * HDIM + d]);
            svt[d * AS + r] = f2tf(qkv[(size_t)(j0 + r) * C3 + 2 * CDIM + h * HDIM + d]);
        }
        __syncthreads();

        // S = Q @ K^T  (16x64 per warp)
        float s[8][4] = {};
        #pragma unroll
        for (int ks = 0; ks < 8; ks++) {
            unsigned af[4];
            const unsigned* p = &sq[(warp * 16 + g) * AS + ks * 8 + tg];
            af[0] = p[0]; af[1] = p[8 * AS]; af[2] = p[4]; af[3] = p[8 * AS + 4];
            #pragma unroll
            for (int nt = 0; nt < 8; nt++) {
                unsigned bf[2];
                const unsigned* q = &sk[(nt * 8 + g) * AS + ks * 8 + tg];
                bf[0] = q[0]; bf[1] = q[4];
                mma8(s[nt], af, bf);
            }
        }

        // Causal mask (only the diagonal tile has masked entries)
        if (j0 == qt * 64) {
            #pragma unroll
            for (int nt = 0; nt < 8; nt++) {
                const int c = j0 + nt * 8 + tg * 2;
                if (c     > rowA)     s[nt][0] = -1e30f;
                if (c + 1 > rowA)     s[nt][1] = -1e30f;
                if (c     > rowA + 8) s[nt][2] = -1e30f;
                if (c + 1 > rowA + 8) s[nt][3] = -1e30f;
            }
        }

        // Row maxima (rows g and g+8), reduce across the 4 threads in the quad
        float mA = -1e30f, mB = -1e30f;
        #pragma unroll
        for (int nt = 0; nt < 8; nt++) {
            mA = fmaxf(mA, fmaxf(s[nt][0], s[nt][1]));
            mB = fmaxf(mB, fmaxf(s[nt][2], s[nt][3]));
        }
        mA = fmaxf(mA, __shfl_xor_sync(0xffffffffu, mA, 1));
        mA = fmaxf(mA, __shfl_xor_sync(0xffffffffu, mA, 2));
        mB = fmaxf(mB, __shfl_xor_sync(0xffffffffu, mB, 1));
        mB = fmaxf(mB, __shfl_xor_sync(0xffffffffu, mB, 2));

        const float mnA = fmaxf(mrun[0], mA);
        const float mnB = fmaxf(mrun[1], mB);
        const float cA  = __expf(mrun[0] - mnA);
        const float cB  = __expf(mrun[1] - mnB);

        float sumA = 0.f, sumB = 0.f;
        #pragma unroll
        for (int nt = 0; nt < 8; nt++) {
            const float p0 = __expf(s[nt][0] - mnA);
            const float p1 = __expf(s[nt][1] - mnA);
            const float p2 = __expf(s[nt][2] - mnB);
            const float p3 = __expf(s[nt][3] - mnB);
            sumA += p0 + p1;
            sumB += p2 + p3;
            unsigned* dst = &sp[(warp * 16 + g) * AS + nt * 8 + tg * 2];
            dst[0] = f2tf(p0); dst[1] = f2tf(p1);
            dst[8 * AS] = f2tf(p2); dst[8 * AS + 1] = f2tf(p3);
            o[nt][0] *= cA; o[nt][1] *= cA;
            o[nt][2] *= cB; o[nt][3] *= cB;
        }
        sumA += __shfl_xor_sync(0xffffffffu, sumA, 1);
        sumA += __shfl_xor_sync(0xffffffffu, sumA, 2);
        sumB += __shfl_xor_sync(0xffffffffu, sumB, 1);
        sumB += __shfl_xor_sync(0xffffffffu, sumB, 2);
        lrun[0] = lrun[0] * cA + sumA;
        lrun[1] = lrun[1] * cB + sumB;
        mrun[0] = mnA;
        mrun[1] = mnB;

        __syncwarp();   // sp writes -> reads within warp

        // O += P @ V   (A = sp rows, B = svt)
        #pragma unroll
        for (int ks = 0; ks < 8; ks++) {
            unsigned af[4];
            const unsigned* p = &sp[(warp * 16 + g) * AS + ks * 8 + tg];
            af[0] = p[0]; af[1] = p[8 * AS]; af[2] = p[4]; af[3] = p[8 * AS + 4];
            #pragma unroll
            for (int nt = 0; nt < 8; nt++) {
                unsigned bf[2];
                const unsigned* q = &svt[(nt * 8 + g) * AS + ks * 8 + tg];
                bf[0] = q[0]; bf[1] = q[4];
                mma8(o[nt], af, bf);
            }
        }
    }

    // Epilogue: normalize and store to g_y
    const float iA = 1.f / lrun[0];
    const float iB = 1.f / lrun[1];
    #pragma unroll
    for (int nt = 0; nt < 8; nt++) {
        const int col = h * HDIM + nt * 8 + tg * 2;
        *(float2*)&g_y[(size_t)(b * SEQ + rowA) * CDIM + col] =
            make_float2(o[nt][0] * iA, o[nt][1] * iA);
        *(float2*)&g_y[(size_t)(b * SEQ + rowA + 8) * CDIM + col] =
            make_float2(o[nt][2] * iB, o[nt][3] * iB);
    }
}

// ---------------------------------------------------------------------------
// Launch
// ---------------------------------------------------------------------------
extern "C" void kernel_launch(void* const* d_in, const int* in_sizes, int n_in,
                              void* d_out, int out_size)
{
    const float* x      = (const float*)d_in[0];  // [B,T,C]
    const float* W_attn = (const float*)d_in[1];  // [C,3C]
    const float* b_attn = (const float*)d_in[2];  // [3C]
    const float* W_proj = (const float*)d_in[3];  // [C,C]
    const float* b_proj = (const float*)d_in[4];  // [C]
    float* out = (float*)d_out;                   // [B,T,C]

    float* qkv = nullptr;
    float* y   = nullptr;
    cudaGetSymbolAddress((void**)&qkv, g_qkv);
    cudaGetSymbolAddress((void**)&y, g_y);

    const int attn_smem = 4 * 64 * AS * sizeof(unsigned);  // 69632 B
    cudaFuncSetAttribute(attn_tf32, cudaFuncAttributeMaxDynamicSharedMemorySize, attn_smem);

    // 1) QKV projection: [8192,1024] @ [1024,3072] + b
    {
        dim3 grid(C3 / 128, BT / 128);
        gemm_tf32<<<grid, 256>>>(x, W_attn, b_attn, qkv, BT, C3, CDIM);
    }
    // 2) Causal flash attention (tensor cores)
    {
        dim3 grid(SEQ / 64, HEADS, BATCH);
        attn_tf32<<<grid, 128, attn_smem>>>();
    }
    // 3) Output projection: [8192,1024] @ [1024,1024] + b
    {
        dim3 grid(CDIM / 128, BT / 128);
        gemm_tf32<<<grid, 256>>>(y, W_proj, b_proj, out, BT, CDIM, CDIM);
    }
}

// round 8
// speedup vs baseline: 4.9462x; 1.2562x over previous
#include <cuda_runtime.h>
#include <cstdint>

// Problem constants
#define BATCH 4
#define SEQ   2048
#define CDIM  1024
#define HEADS 16
#define HDIM  64
#define BT    (BATCH * SEQ)       // 8192 rows
#define C3    (3 * CDIM)          // 3072

// Scratch in device globals (no dynamic allocation allowed)
__device__ float g_qkv[(size_t)BT * C3];     // [B*T, 3C]
__device__ float g_y[(size_t)BT * CDIM];     // [B*T, C] attn out (pre-rounded tf32)
__device__ float g_xr[(size_t)BT * CDIM];    // x rounded to tf32
__device__ float g_war[(size_t)C3 * CDIM];   // W_attn^T [3C][C], rounded
__device__ float g_wpr[(size_t)CDIM * CDIM]; // W_proj^T [C][C], rounded

// ---------------------------------------------------------------------------
// Helpers
// ---------------------------------------------------------------------------
__device__ __forceinline__ unsigned f2tf(float f) {
    unsigned r;
    asm("cvt.rna.tf32.f32 %0, %1;" : "=r"(r) : "f"(f));
    return r;
}

__device__ __forceinline__ uint32_t smem_u32(const void* p) {
    uint32_t a;
    asm("{ .reg .u64 t; cvta.to.shared.u64 t, %1; cvt.u32.u64 %0, t; }"
        : "=r"(a) : "l"(p));
    return a;
}

__device__ __forceinline__ void mma8(float* c, const unsigned* a, const unsigned* b) {
    asm volatile(
        "mma.sync.aligned.m16n8k8.row.col.f32.tf32.tf32.f32 "
        "{%0,%1,%2,%3}, {%4,%5,%6,%7}, {%8,%9}, {%0,%1,%2,%3};"
        : "+f"(c[0]), "+f"(c[1]), "+f"(c[2]), "+f"(c[3])
        : "r"(a[0]), "r"(a[1]), "r"(a[2]), "r"(a[3]), "r"(b[0]), "r"(b[1]));
}

#define LDSM4(r0, r1, r2, r3, addr)                                           \
    asm volatile("ldmatrix.sync.aligned.m8n8.x4.shared.b16 {%0,%1,%2,%3}, [%4];" \
                 : "=r"(r0), "=r"(r1), "=r"(r2), "=r"(r3) : "r"(addr))

#define CP16(dst, src)                                                        \
    asm volatile("cp.async.cg.shared.global [%0], [%1], 16;"                  \
                 :: "r"(dst), "l"(src))
#define CP_COMMIT() asm volatile("cp.async.commit_group;" ::: "memory")
#define CP_WAIT(n)  asm volatile("cp.async.wait_group %0;" :: "n"(n) : "memory")

// ---------------------------------------------------------------------------
// Preprocessing: tf32-round (and transpose for weights)
// ---------------------------------------------------------------------------
__global__ void round_pass(const float* __restrict__ src, float* __restrict__ dst) {
    const int i = blockIdx.x * blockDim.x + threadIdx.x;
    float4 v = ((const float4*)src)[i];
    v.x = __uint_as_float(f2tf(v.x));
    v.y = __uint_as_float(f2tf(v.y));
    v.z = __uint_as_float(f2tf(v.z));
    v.w = __uint_as_float(f2tf(v.w));
    ((float4*)dst)[i] = v;
}

// W[K][N] -> WT[N][K], rounded to tf32
__global__ void wtrans(const float* __restrict__ W, float* __restrict__ WT,
                       int K, int N) {
    __shared__ float t[32][33];
    const int n0 = blockIdx.x * 32, k0 = blockIdx.y * 32;
    const int tx = threadIdx.x, ty = threadIdx.y;
    #pragma unroll
    for (int j = 0; j < 4; j++)
        t[ty + 8 * j][tx] = W[(size_t)(k0 + ty + 8 * j) * N + n0 + tx];
    __syncthreads();
    #pragma unroll
    for (int j = 0; j < 4; j++)
        WT[(size_t)(n0 + ty + 8 * j) * K + k0 + tx] =
            __uint_as_float(f2tf(t[tx][ty + 8 * j]));
}

// ---------------------------------------------------------------------------
// TF32 GEMM: C[M,N] = A[M,K] @ Bt[N,K]^T + bias[N]
// A, Bt pre-rounded to tf32. Block tile 128x256, K-chunk 32, 256 threads,
// 8 warps (2x4), warp tile 64x64. cp.async 4-stage pipeline, ldmatrix frags.
// SMEM rows: 128B (32 tf32), XOR-swizzled 16B chunks: chunk' = chunk ^ (row&7).
// ---------------------------------------------------------------------------
#define BM 128
#define BN 256
#define GSTAGE 49152           // 16KB A + 32KB B
#define GSB_OFF 16384
#define GEMM_SMEM (4 * GSTAGE) // 196608

__global__ __launch_bounds__(256, 1) void gemm_tc(
    const float* __restrict__ A, const float* __restrict__ Bt,
    const float* __restrict__ bias, float* __restrict__ C,
    int M, int N, int K)
{
    extern __shared__ char sm[];
    const uint32_t sb = smem_u32(sm);
    const int tid  = threadIdx.x;
    const int lane = tid & 31;
    const int warp = tid >> 5;
    const int g    = lane >> 2;
    const int tg   = lane & 3;
    const int m0 = blockIdx.y * BM;
    const int n0 = blockIdx.x * BN;
    const int wm = (warp >> 2) * 64;
    const int wn = (warp & 3) * 64;

    // cp.async mapping: thread t covers rows (t>>3)+32j, fixed 16B chunk t&7
    const int ar  = tid >> 3;
    const int ach = tid & 7;
    const uint32_t sca = (uint32_t)((ach ^ (ar & 7)) * 16);  // swizzled chunk byte off
    const float* aSrc = A  + (size_t)(m0 + ar) * K + ach * 4;
    const float* bSrc = Bt + (size_t)(n0 + ar) * K + ach * 4;

    // ldmatrix lane addressing components
    const uint32_t alr = lane & 7;                                  // row&7
    const uint32_t aRowL = (lane & 7) + ((lane >> 3) & 1) * 8;      // A row-in-16
    const uint32_t aChL  = (lane >> 4);                             // A chunk half
    const uint32_t bRowL = (lane & 7) + ((lane >> 4) & 1) * 8;      // B row-in-16
    const uint32_t bChL  = (lane >> 3) & 1;                         // B chunk half

    float acc[4][8][4] = {};
    const int nch = K / 32;

    // prologue: stages 0..2
    #pragma unroll
    for (int s = 0; s < 3; s++) {
        const uint32_t st = sb + s * GSTAGE;
        const int k0 = s * 32;
        #pragma unroll
        for (int j = 0; j < 4; j++)
            CP16(st + (uint32_t)(ar + 32 * j) * 128 + sca,
                 aSrc + k0 + (size_t)j * 32 * K);
        #pragma unroll
        for (int j = 0; j < 8; j++)
            CP16(st + GSB_OFF + (uint32_t)(ar + 32 * j) * 128 + sca,
                 bSrc + k0 + (size_t)j * 32 * K);
        CP_COMMIT();
    }

    for (int i = 0; i < nch; i++) {
        CP_WAIT(2);
        __syncthreads();

        // issue stage i+3 (overwrites stage used in iter i-1; safe post-sync)
        if (i + 3 < nch) {
            const uint32_t st = sb + ((i + 3) & 3) * GSTAGE;
            const int k0 = (i + 3) * 32;
            #pragma unroll
            for (int j = 0; j < 4; j++)
                CP16(st + (uint32_t)(ar + 32 * j) * 128 + sca,
                     aSrc + k0 + (size_t)j * 32 * K);
            #pragma unroll
            for (int j = 0; j < 8; j++)
                CP16(st + GSB_OFF + (uint32_t)(ar + 32 * j) * 128 + sca,
                     bSrc + k0 + (size_t)j * 32 * K);
        }
        CP_COMMIT();

        // compute on stage i
        const uint32_t stA = sb + (i & 3) * GSTAGE;
        const uint32_t stB = stA + GSB_OFF;
        #pragma unroll
        for (int ks = 0; ks < 4; ks++) {
            unsigned af[4][4];
            #pragma unroll
            for (int mt = 0; mt < 4; mt++) {
                const uint32_t addr = stA
                    + (uint32_t)(wm + mt * 16 + aRowL) * 128
                    + (((2u * ks + aChL) ^ alr) * 16);
                LDSM4(af[mt][0], af[mt][1], af[mt][2], af[mt][3], addr);
            }
            unsigned bf[8][2];
            #pragma unroll
            for (int p = 0; p < 4; p++) {
                const uint32_t addr = stB
                    + (uint32_t)(wn + p * 16 + bRowL) * 128
                    + (((2u * ks + bChL) ^ alr) * 16);
                LDSM4(bf[2 * p][0], bf[2 * p][1], bf[2 * p + 1][0], bf[2 * p + 1][1], addr);
            }
            #pragma unroll
            for (int mt = 0; mt < 4; mt++)
                #pragma unroll
                for (int nt = 0; nt < 8; nt++)
                    mma8(acc[mt][nt], af[mt], bf[nt]);
        }
    }

    // epilogue: bias + store
    #pragma unroll
    for (int mt = 0; mt < 4; mt++) {
        const int r0 = m0 + wm + mt * 16 + g;
        #pragma unroll
        for (int nt = 0; nt < 8; nt++) {
            const int c0 = n0 + wn + nt * 8 + tg * 2;
            const float b0v = bias[c0], b1v = bias[c0 + 1];
            *(float2*)&C[(size_t)r0 * N + c0] =
                make_float2(acc[mt][nt][0] + b0v, acc[mt][nt][1] + b1v);
            *(float2*)&C[(size_t)(r0 + 8) * N + c0] =
                make_float2(acc[mt][nt][2] + b0v, acc[mt][nt][3] + b1v);
        }
    }
}

// ---------------------------------------------------------------------------
// Flash attention (causal), tf32 mma.sync + ldmatrix.
// Block = (64-row Q tile, head, batch). 128 threads = 4 warps.
// SMEM arrays have row stride 68 floats (272B) -> ldmatrix conflict-free.
// ---------------------------------------------------------------------------
#define AS 68
#define ROWB (AS * 4)   // 272 bytes per row

__global__ __launch_bounds__(128) void attn_tf32()
{
    extern __shared__ unsigned asmem[];
    unsigned* sq  = asmem;             // [64][AS]
    unsigned* sk  = sq  + 64 * AS;
    unsigned* svt = sk  + 64 * AS;
    unsigned* sp  = svt + 64 * AS;
    const uint32_t base = smem_u32(asmem);
    const uint32_t sqb  = base;
    const uint32_t skb  = base + 64 * ROWB;
    const uint32_t svtb = base + 2 * 64 * ROWB;
    const uint32_t spb  = base + 3 * 64 * ROWB;

    const int tid  = threadIdx.x;
    const int lane = tid & 31;
    const int warp = tid >> 5;
    const int g    = lane >> 2;
    const int tg   = lane & 3;

    const uint32_t aRowL = (lane & 7) + ((lane >> 3) & 1) * 8;
    const uint32_t aChL  = (lane >> 4);
    const uint32_t bRowL = (lane & 7) + ((lane >> 4) & 1) * 8;
    const uint32_t bChL  = (lane >> 3) & 1;

    const int qt = blockIdx.x;
    const int h  = blockIdx.y;
    const int b  = blockIdx.z;
    const float* qkv = g_qkv + (size_t)b * SEQ * C3;

    const int d  = tid & 63;
    const int rh = tid >> 6;

    for (int it = 0; it < 32; it++) {
        const int r = it * 2 + rh;
        sq[r * AS + d] = f2tf(qkv[(size_t)(qt * 64 + r) * C3 + h * HDIM + d] * 0.125f);
    }

    float o[8][4] = {};
    float mrun[2] = {-1e30f, -1e30f};
    float lrun[2] = {0.f, 0.f};
    const int rowA = qt * 64 + warp * 16 + g;

    for (int j0 = 0; j0 <= qt * 64; j0 += 64) {
        __syncthreads();
        for (int it = 0; it < 32; it++) {
            const int r = it * 2 + rh;
            sk[r * AS + d]  = f2tf(qkv[(size_t)(j0 + r) * C3 + CDIM     + h * HDIM + d]);
            svt[d * AS + r] = f2tf(qkv[(size_t)(j0 + r) * C3 + 2 * CDIM + h * HDIM + d]);
        }
        __syncthreads();

        // S = Q @ K^T
        float s[8][4] = {};
        #pragma unroll
        for (int ks = 0; ks < 8; ks++) {
            unsigned af[4];
            LDSM4(af[0], af[1], af[2], af[3],
                  sqb + (uint32_t)(warp * 16 + aRowL) * ROWB + (2u * ks + aChL) * 16);
            unsigned bf[8][2];
            #pragma unroll
            for (int p = 0; p < 4; p++)
                LDSM4(bf[2 * p][0], bf[2 * p][1], bf[2 * p + 1][0], bf[2 * p + 1][1],
                      skb + (uint32_t)(p * 16 + bRowL) * ROWB + (2u * ks + bChL) * 16);
            #pragma unroll
            for (int nt = 0; nt < 8; nt++)
                mma8(s[nt], af, bf[nt]);
        }

        if (j0 == qt * 64) {
            #pragma unroll
            for (int nt = 0; nt < 8; nt++) {
                const int c = j0 + nt * 8 + tg * 2;
                if (c     > rowA)     s[nt][0] = -1e30f;
                if (c + 1 > rowA)     s[nt][1] = -1e30f;
                if (c     > rowA + 8) s[nt][2] = -1e30f;
                if (c + 1 > rowA + 8) s[nt][3] = -1e30f;
            }
        }

        float mA = -1e30f, mB = -1e30f;
        #pragma unroll
        for (int nt = 0; nt < 8; nt++) {
            mA = fmaxf(mA, fmaxf(s[nt][0], s[nt][1]));
            mB = fmaxf(mB, fmaxf(s[nt][2], s[nt][3]));
        }
        mA = fmaxf(mA, __shfl_xor_sync(0xffffffffu, mA, 1));
        mA = fmaxf(mA, __shfl_xor_sync(0xffffffffu, mA, 2));
        mB = fmaxf(mB, __shfl_xor_sync(0xffffffffu, mB, 1));
        mB = fmaxf(mB, __shfl_xor_sync(0xffffffffu, mB, 2));

        const float mnA = fmaxf(mrun[0], mA);
        const float mnB = fmaxf(mrun[1], mB);
        const float cA  = __expf(mrun[0] - mnA);
        const float cB  = __expf(mrun[1] - mnB);

        float sumA = 0.f, sumB = 0.f;
        #pragma unroll
        for (int nt = 0; nt < 8; nt++) {
            const float p0 = __expf(s[nt][0] - mnA);
            const float p1 = __expf(s[nt][1] - mnA);
            const float p2 = __expf(s[nt][2] - mnB);
            const float p3 = __expf(s[nt][3] - mnB);
            sumA += p0 + p1;
            sumB += p2 + p3;
            unsigned* dst = &sp[(warp * 16 + g) * AS + nt * 8 + tg * 2];
            dst[0] = f2tf(p0); dst[1] = f2tf(p1);
            dst[8 * AS] = f2tf(p2); dst[8 * AS + 1] = f2tf(p3);
            o[nt][0] *= cA; o[nt][1] *= cA;
            o[nt][2] *= cB; o[nt][3] *= cB;
        }
        sumA += __shfl_xor_sync(0xffffffffu, sumA, 1);
        sumA += __shfl_xor_sync(0xffffffffu, sumA, 2);
        sumB += __shfl_xor_sync(0xffffffffu, sumB, 1);
        sumB += __shfl_xor_sync(0xffffffffu, sumB, 2);
        lrun[0] = lrun[0] * cA + sumA;
        lrun[1] = lrun[1] * cB + sumB;
        mrun[0] = mnA;
        mrun[1] = mnB;

        __syncwarp();

        // O += P @ V
        #pragma unroll
        for (int ks = 0; ks < 8; ks++) {
            unsigned af[4];
            LDSM4(af[0], af[1], af[2], af[3],
                  spb + (uint32_t)(warp * 16 + aRowL) * ROWB + (2u * ks + aChL) * 16);
            unsigned bf[8][2];
            #pragma unroll
            for (int p = 0; p < 4; p++)
                LDSM4(bf[2 * p][0], bf[2 * p][1], bf[2 * p + 1][0], bf[2 * p + 1][1],
                      svtb + (uint32_t)(p * 16 + bRowL) * ROWB + (2u * ks + bChL) * 16);
            #pragma unroll
            for (int nt = 0; nt < 8; nt++)
                mma8(o[nt], af, bf[nt]);
        }
    }

    // epilogue: normalize, round to tf32 (proj GEMM consumes raw bits), store
    const float iA = 1.f / lrun[0];
    const float iB = 1.f / lrun[1];
    #pragma unroll
    for (int nt = 0; nt < 8; nt++) {
        const int col = h * HDIM + nt * 8 + tg * 2;
        *(float2*)&g_y[(size_t)(b * SEQ + rowA) * CDIM + col] = make_float2(
            __uint_as_float(f2tf(o[nt][0] * iA)), __uint_as_float(f2tf(o[nt][1] * iA)));
        *(float2*)&g_y[(size_t)(b * SEQ + rowA + 8) * CDIM + col] = make_float2(
            __uint_as_float(f2tf(o[nt][2] * iB)), __uint_as_float(f2tf(o[nt][3] * iB)));
    }
}

// ---------------------------------------------------------------------------
// Launch
// ---------------------------------------------------------------------------
extern "C" void kernel_launch(void* const* d_in, const int* in_sizes, int n_in,
                              void* d_out, int out_size)
{
    const float* x      = (const float*)d_in[0];  // [B,T,C]
    const float* W_attn = (const float*)d_in[1];  // [C,3C]
    const float* b_attn = (const float*)d_in[2];  // [3C]
    const float* W_proj = (const float*)d_in[3];  // [C,C]
    const float* b_proj = (const float*)d_in[4];  // [C]
    float* out = (float*)d_out;                   // [B,T,C]

    float *qkv, *y, *xr, *war, *wpr;
    cudaGetSymbolAddress((void**)&qkv, g_qkv);
    cudaGetSymbolAddress((void**)&y,   g_y);
    cudaGetSymbolAddress((void**)&xr,  g_xr);
    cudaGetSymbolAddress((void**)&war, g_war);
    cudaGetSymbolAddress((void**)&wpr, g_wpr);

    const int attn_smem = 4 * 64 * AS * sizeof(unsigned);  // 69632
    cudaFuncSetAttribute(attn_tf32, cudaFuncAttributeMaxDynamicSharedMemorySize, attn_smem);
    cudaFuncSetAttribute(gemm_tc,   cudaFuncAttributeMaxDynamicSharedMemorySize, GEMM_SMEM);

    // 0) Preprocess: round x, transpose+round weights
    round_pass<<<(BT * CDIM) / (4 * 256), 256>>>(x, xr);
    wtrans<<<dim3(C3 / 32, CDIM / 32), dim3(32, 8)>>>(W_attn, war, CDIM, C3);
    wtrans<<<dim3(CDIM / 32, CDIM / 32), dim3(32, 8)>>>(W_proj, wpr, CDIM, CDIM);

    // 1) QKV projection: [8192,1024] @ [1024,3072] + b
    gemm_tc<<<dim3(C3 / BN, BT / BM), 256, GEMM_SMEM>>>(xr, war, b_attn, qkv,
                                                        BT, C3, CDIM);
    // 2) Causal flash attention
    attn_tf32<<<dim3(SEQ / 64, HEADS, BATCH), 128, attn_smem>>>();

    // 3) Output projection: [8192,1024] @ [1024,1024] + b
    gemm_tc<<<dim3(CDIM / BN, BT / BM), 256, GEMM_SMEM>>>(y, wpr, b_proj, out,
                                                          BT, CDIM, CDIM);
}

// round 9
// speedup vs baseline: 5.2796x; 1.0674x over previous
#include <cuda_runtime.h>
#include <cstdint>

// Problem constants
#define BATCH 4
#define SEQ   2048
#define CDIM  1024
#define HEADS 16
#define HDIM  64
#define BT    (BATCH * SEQ)       // 8192 rows
#define C3    (3 * CDIM)          // 3072

// Scratch in device globals (no dynamic allocation allowed)
__device__ float g_qkv[(size_t)BT * C3];     // [B*T, 3C]  (pre-rounded tf32)
__device__ float g_y[(size_t)BT * CDIM];     // [B*T, C] attn out (pre-rounded tf32)
__device__ float g_xr[(size_t)BT * CDIM];    // x rounded to tf32
__device__ float g_war[(size_t)C3 * CDIM];   // W_attn^T [3C][C], rounded
__device__ float g_wpr[(size_t)CDIM * CDIM]; // W_proj^T [C][C], rounded

// ---------------------------------------------------------------------------
// Helpers
// ---------------------------------------------------------------------------
__device__ __forceinline__ unsigned f2tf(float f) {
    unsigned r;
    asm("cvt.rna.tf32.f32 %0, %1;" : "=r"(r) : "f"(f));
    return r;
}

__device__ __forceinline__ uint32_t smem_u32(const void* p) {
    uint32_t a;
    asm("{ .reg .u64 t; cvta.to.shared.u64 t, %1; cvt.u32.u64 %0, t; }"
        : "=r"(a) : "l"(p));
    return a;
}

__device__ __forceinline__ void mma8(float* c, const unsigned* a, const unsigned* b) {
    asm volatile(
        "mma.sync.aligned.m16n8k8.row.col.f32.tf32.tf32.f32 "
        "{%0,%1,%2,%3}, {%4,%5,%6,%7}, {%8,%9}, {%0,%1,%2,%3};"
        : "+f"(c[0]), "+f"(c[1]), "+f"(c[2]), "+f"(c[3])
        : "r"(a[0]), "r"(a[1]), "r"(a[2]), "r"(a[3]), "r"(b[0]), "r"(b[1]));
}

#define LDSM4(r0, r1, r2, r3, addr)                                           \
    asm volatile("ldmatrix.sync.aligned.m8n8.x4.shared.b16 {%0,%1,%2,%3}, [%4];" \
                 : "=r"(r0), "=r"(r1), "=r"(r2), "=r"(r3) : "r"(addr))

#define CP16(dst, src)                                                        \
    asm volatile("cp.async.cg.shared.global [%0], [%1], 16;"                  \
                 :: "r"(dst), "l"(src))
#define CP_COMMIT() asm volatile("cp.async.commit_group;" ::: "memory")
#define CP_WAIT(n)  asm volatile("cp.async.wait_group %0;" :: "n"(n) : "memory")

// ---------------------------------------------------------------------------
// Preprocessing: tf32-round (and transpose for weights)
// ---------------------------------------------------------------------------
__global__ void round_pass(const float* __restrict__ src, float* __restrict__ dst) {
    const int i = blockIdx.x * blockDim.x + threadIdx.x;
    float4 v = ((const float4*)src)[i];
    v.x = __uint_as_float(f2tf(v.x));
    v.y = __uint_as_float(f2tf(v.y));
    v.z = __uint_as_float(f2tf(v.z));
    v.w = __uint_as_float(f2tf(v.w));
    ((float4*)dst)[i] = v;
}

// W[K][N] -> WT[N][K], rounded to tf32
__global__ void wtrans(const float* __restrict__ W, float* __restrict__ WT,
                       int K, int N) {
    __shared__ float t[32][33];
    const int n0 = blockIdx.x * 32, k0 = blockIdx.y * 32;
    const int tx = threadIdx.x, ty = threadIdx.y;
    #pragma unroll
    for (int j = 0; j < 4; j++)
        t[ty + 8 * j][tx] = W[(size_t)(k0 + ty + 8 * j) * N + n0 + tx];
    __syncthreads();
    #pragma unroll
    for (int j = 0; j < 4; j++)
        WT[(size_t)(n0 + ty + 8 * j) * K + k0 + tx] =
            __uint_as_float(f2tf(t[tx][ty + 8 * j]));
}

// ---------------------------------------------------------------------------
// TF32 GEMM: C[M,N] = A[M,K] @ Bt[N,K]^T + bias[N]  (optionally round output)
// Block tile 128x256, K-chunk 32, 256 threads, warp tile 64x64.
// cp.async 4-stage pipeline, ldmatrix frags, XOR-swizzled 128B smem rows.
// ---------------------------------------------------------------------------
#define BM 128
#define BN 256
#define GSTAGE 49152           // 16KB A + 32KB B
#define GSB_OFF 16384
#define GEMM_SMEM (4 * GSTAGE) // 196608

__global__ __launch_bounds__(256, 1) void gemm_tc(
    const float* __restrict__ A, const float* __restrict__ Bt,
    const float* __restrict__ bias, float* __restrict__ C,
    int M, int N, int K, int roundOut)
{
    extern __shared__ char sm[];
    const uint32_t sb = smem_u32(sm);
    const int tid  = threadIdx.x;
    const int lane = tid & 31;
    const int warp = tid >> 5;
    const int g    = lane >> 2;
    const int tg   = lane & 3;
    const int m0 = blockIdx.y * BM;
    const int n0 = blockIdx.x * BN;
    const int wm = (warp >> 2) * 64;
    const int wn = (warp & 3) * 64;

    const int ar  = tid >> 3;
    const int ach = tid & 7;
    const uint32_t sca = (uint32_t)((ach ^ (ar & 7)) * 16);
    const float* aSrc = A  + (size_t)(m0 + ar) * K + ach * 4;
    const float* bSrc = Bt + (size_t)(n0 + ar) * K + ach * 4;

    const uint32_t alr = lane & 7;
    const uint32_t aRowL = (lane & 7) + ((lane >> 3) & 1) * 8;
    const uint32_t aChL  = (lane >> 4);
    const uint32_t bRowL = (lane & 7) + ((lane >> 4) & 1) * 8;
    const uint32_t bChL  = (lane >> 3) & 1;

    float acc[4][8][4] = {};
    const int nch = K / 32;

    #pragma unroll
    for (int s = 0; s < 3; s++) {
        const uint32_t st = sb + s * GSTAGE;
        const int k0 = s * 32;
        #pragma unroll
        for (int j = 0; j < 4; j++)
            CP16(st + (uint32_t)(ar + 32 * j) * 128 + sca,
                 aSrc + k0 + (size_t)j * 32 * K);
        #pragma unroll
        for (int j = 0; j < 8; j++)
            CP16(st + GSB_OFF + (uint32_t)(ar + 32 * j) * 128 + sca,
                 bSrc + k0 + (size_t)j * 32 * K);
        CP_COMMIT();
    }

    for (int i = 0; i < nch; i++) {
        CP_WAIT(2);
        __syncthreads();

        if (i + 3 < nch) {
            const uint32_t st = sb + ((i + 3) & 3) * GSTAGE;
            const int k0 = (i + 3) * 32;
            #pragma unroll
            for (int j = 0; j < 4; j++)
                CP16(st + (uint32_t)(ar + 32 * j) * 128 + sca,
                     aSrc + k0 + (size_t)j * 32 * K);
            #pragma unroll
            for (int j = 0; j < 8; j++)
                CP16(st + GSB_OFF + (uint32_t)(ar + 32 * j) * 128 + sca,
                     bSrc + k0 + (size_t)j * 32 * K);
        }
        CP_COMMIT();

        const uint32_t stA = sb + (i & 3) * GSTAGE;
        const uint32_t stB = stA + GSB_OFF;
        #pragma unroll
        for (int ks = 0; ks < 4; ks++) {
            unsigned af[4][4];
            #pragma unroll
            for (int mt = 0; mt < 4; mt++) {
                const uint32_t addr = stA
                    + (uint32_t)(wm + mt * 16 + aRowL) * 128
                    + (((2u * ks + aChL) ^ alr) * 16);
                LDSM4(af[mt][0], af[mt][1], af[mt][2], af[mt][3], addr);
            }
            unsigned bf[8][2];
            #pragma unroll
            for (int p = 0; p < 4; p++) {
                const uint32_t addr = stB
                    + (uint32_t)(wn + p * 16 + bRowL) * 128
                    + (((2u * ks + bChL) ^ alr) * 16);
                LDSM4(bf[2 * p][0], bf[2 * p][1], bf[2 * p + 1][0], bf[2 * p + 1][1], addr);
            }
            #pragma unroll
            for (int mt = 0; mt < 4; mt++)
                #pragma unroll
                for (int nt = 0; nt < 8; nt++)
                    mma8(acc[mt][nt], af[mt], bf[nt]);
        }
    }

    #pragma unroll
    for (int mt = 0; mt < 4; mt++) {
        const int r0 = m0 + wm + mt * 16 + g;
        #pragma unroll
        for (int nt = 0; nt < 8; nt++) {
            const int c0 = n0 + wn + nt * 8 + tg * 2;
            const float b0v = bias[c0], b1v = bias[c0 + 1];
            float v0 = acc[mt][nt][0] + b0v, v1 = acc[mt][nt][1] + b1v;
            float v2 = acc[mt][nt][2] + b0v, v3 = acc[mt][nt][3] + b1v;
            if (roundOut) {
                v0 = __uint_as_float(f2tf(v0)); v1 = __uint_as_float(f2tf(v1));
                v2 = __uint_as_float(f2tf(v2)); v3 = __uint_as_float(f2tf(v3));
            }
            *(float2*)&C[(size_t)r0 * N + c0] = make_float2(v0, v1);
            *(float2*)&C[(size_t)(r0 + 8) * N + c0] = make_float2(v2, v3);
        }
    }
}

// ---------------------------------------------------------------------------
// Flash attention (causal), tf32 mma.sync, cp.async pipelined.
// Block = (128-row Q tile, head, batch). 256 threads = 8 warps;
// warp w owns q rows [w*16, w*16+16). KV tiles of 64 rows, double-buffered.
// g_qkv is pre-rounded tf32 -> raw cp.async loads.
// SMEM rows: 64 floats @ 272B stride (ldmatrix conflict-free).
// Layout: sp (Q staging, then P) [128][68] | K double buf | V double buf.
// ---------------------------------------------------------------------------
#define ATT_SP   0
#define ATT_K(s) (34816 + (s) * 17408)
#define ATT_V(s) (69632 + (s) * 17408)
#define ATT_SMEM 104448

__global__ __launch_bounds__(256, 1) void attn_tc()
{
    extern __shared__ char attsm[];
    const uint32_t base = smem_u32(attsm);

    const int tid  = threadIdx.x;
    const int lane = tid & 31;
    const int warp = tid >> 5;          // 0..7
    const int g    = lane >> 2;
    const int tg   = lane & 3;

    const uint32_t aRowL = (lane & 7) + ((lane >> 3) & 1) * 8;
    const uint32_t aChL  = (lane >> 4);
    const uint32_t bRowL = (lane & 7) + ((lane >> 4) & 1) * 8;
    const uint32_t bChL  = (lane >> 3) & 1;

    const int qt = (gridDim.x - 1) - blockIdx.x;   // big tiles first
    const int h  = blockIdx.y;
    const int b  = blockIdx.z;
    const float* qkv = g_qkv + (size_t)b * SEQ * C3;

    // cp.async mapping: 64-row tile = 64 rows x 16 chunks of 16B
    const int r16 = tid >> 4;           // 0..15
    const int ch  = tid & 15;           // 0..15

    // --- Load Q (128 rows) into sp ---
    const float* qsrc = qkv + (size_t)(qt * 128 + r16) * C3 + h * HDIM + ch * 4;
    #pragma unroll
    for (int j = 0; j < 8; j++)
        CP16(base + ATT_SP + (uint32_t)(r16 + 16 * j) * 272 + ch * 16,
             qsrc + (size_t)(16 * j) * C3);
    CP_COMMIT();

    const float* ksrc = qkv + (size_t)r16 * C3 + CDIM     + h * HDIM + ch * 4;
    const float* vsrc = qkv + (size_t)r16 * C3 + 2 * CDIM + h * HDIM + ch * 4;

    // --- Prefetch KV tile 0 into buf 0 ---
    #pragma unroll
    for (int j = 0; j < 4; j++) {
        CP16(base + ATT_K(0) + (uint32_t)(r16 + 16 * j) * 272 + ch * 16,
             ksrc + (size_t)(16 * j) * C3);
        CP16(base + ATT_V(0) + (uint32_t)(r16 + 16 * j) * 272 + ch * 16,
             vsrc + (size_t)(16 * j) * C3);
    }
    CP_COMMIT();

    CP_WAIT(1);          // Q complete (tile 0 may still be in flight)
    __syncthreads();

    // --- Q fragments to registers (warp-private rows) ---
    unsigned aq[8][4];
    #pragma unroll
    for (int ks = 0; ks < 8; ks++)
        LDSM4(aq[ks][0], aq[ks][1], aq[ks][2], aq[ks][3],
              base + ATT_SP + (uint32_t)(warp * 16 + aRowL) * 272
                            + (2u * ks + aChL) * 16);

    float o[8][4] = {};
    float mrun[2] = {-1e30f, -1e30f};
    float lrun[2] = {0.f, 0.f};
    const int rowA = qt * 128 + warp * 16 + g;      // rows g / g+8
    const int qmax = qt * 128 + warp * 16 + 15;

    const int ntiles = 2 * qt + 2;
    for (int i = 0; i < ntiles; i++) {
        __syncthreads();        // all warps done with buf (i+1)&1's previous tile
        if (i + 1 < ntiles) {
            const uint32_t kb = base + ATT_K((i + 1) & 1);
            const uint32_t vb = base + ATT_V((i + 1) & 1);
            const size_t roff = (size_t)(i + 1) * 64 * C3;
            #pragma unroll
            for (int j = 0; j < 4; j++) {
                CP16(kb + (uint32_t)(r16 + 16 * j) * 272 + ch * 16,
                     ksrc + roff + (size_t)(16 * j) * C3);
                CP16(vb + (uint32_t)(r16 + 16 * j) * 272 + ch * 16,
                     vsrc + roff + (size_t)(16 * j) * C3);
            }
            CP_COMMIT();
            CP_WAIT(1);
        } else {
            CP_WAIT(0);
        }
        __syncthreads();        // tile i visible to all warps

        const int jbase = i * 64;
        if (jbase > qmax) continue;     // fully-masked warp: contributes nothing

        const uint32_t kb = base + ATT_K(i & 1);
        const unsigned* sv = (const unsigned*)(attsm + ATT_V(i & 1));

        // S = Q @ K^T  (16 x 64 per warp)
        float s[8][4] = {};
        #pragma unroll
        for (int ks = 0; ks < 8; ks++) {
            unsigned bf[8][2];
            #pragma unroll
            for (int p = 0; p < 4; p++)
                LDSM4(bf[2 * p][0], bf[2 * p][1], bf[2 * p + 1][0], bf[2 * p + 1][1],
                      kb + (uint32_t)(p * 16 + bRowL) * 272 + (2u * ks + bChL) * 16);
            #pragma unroll
            for (int nt = 0; nt < 8; nt++)
                mma8(s[nt], aq[ks], bf[nt]);
        }

        // scale by 1/sqrt(D) (exact power of 2; Q,K were pre-rounded tf32)
        #pragma unroll
        for (int nt = 0; nt < 8; nt++) {
            s[nt][0] *= 0.125f; s[nt][1] *= 0.125f;
            s[nt][2] *= 0.125f; s[nt][3] *= 0.125f;
        }

        // causal mask (only tiles overlapping the diagonal)
        if (i >= 2 * qt) {
            #pragma unroll
            for (int nt = 0; nt < 8; nt++) {
                const int c = jbase + nt * 8 + tg * 2;
                if (c     > rowA)     s[nt][0] = -1e30f;
                if (c + 1 > rowA)     s[nt][1] = -1e30f;
                if (c     > rowA + 8) s[nt][2] = -1e30f;
                if (c + 1 > rowA + 8) s[nt][3] = -1e30f;
            }
        }

        // online softmax
        float mA = -1e30f, mB = -1e30f;
        #pragma unroll
        for (int nt = 0; nt < 8; nt++) {
            mA = fmaxf(mA, fmaxf(s[nt][0], s[nt][1]));
            mB = fmaxf(mB, fmaxf(s[nt][2], s[nt][3]));
        }
        mA = fmaxf(mA, __shfl_xor_sync(0xffffffffu, mA, 1));
        mA = fmaxf(mA, __shfl_xor_sync(0xffffffffu, mA, 2));
        mB = fmaxf(mB, __shfl_xor_sync(0xffffffffu, mB, 1));
        mB = fmaxf(mB, __shfl_xor_sync(0xffffffffu, mB, 2));

        const float mnA = fmaxf(mrun[0], mA);
        const float mnB = fmaxf(mrun[1], mB);
        const float cA  = __expf(mrun[0] - mnA);
        const float cB  = __expf(mrun[1] - mnB);

        float sumA = 0.f, sumB = 0.f;
        unsigned* sp = (unsigned*)(attsm + ATT_SP);
        #pragma unroll
        for (int nt = 0; nt < 8; nt++) {
            const float p0 = __expf(s[nt][0] - mnA);
            const float p1 = __expf(s[nt][1] - mnA);
            const float p2 = __expf(s[nt][2] - mnB);
            const float p3 = __expf(s[nt][3] - mnB);
            sumA += p0 + p1;
            sumB += p2 + p3;
            unsigned* dst = &sp[(warp * 16 + g) * 68 + nt * 8 + tg * 2];
            dst[0] = f2tf(p0); dst[1] = f2tf(p1);
            dst[8 * 68] = f2tf(p2); dst[8 * 68 + 1] = f2tf(p3);
            o[nt][0] *= cA; o[nt][1] *= cA;
            o[nt][2] *= cB; o[nt][3] *= cB;
        }
        sumA += __shfl_xor_sync(0xffffffffu, sumA, 1);
        sumA += __shfl_xor_sync(0xffffffffu, sumA, 2);
        sumB += __shfl_xor_sync(0xffffffffu, sumB, 1);
        sumB += __shfl_xor_sync(0xffffffffu, sumB, 2);
        lrun[0] = lrun[0] * cA + sumA;
        lrun[1] = lrun[1] * cB + sumB;
        mrun[0] = mnA;
        mrun[1] = mnB;

        __syncwarp();   // P STS -> LDSM (warp-private rows)

        // O += P @ V   (B frags from natural-layout V via scalar LDS)
        #pragma unroll
        for (int ks = 0; ks < 8; ks++) {
            unsigned af[4];
            LDSM4(af[0], af[1], af[2], af[3],
                  base + ATT_SP + (uint32_t)(warp * 16 + aRowL) * 272
                                + (2u * ks + aChL) * 16);
            #pragma unroll
            for (int nt = 0; nt < 8; nt++) {
                unsigned bfv[2];
                bfv[0] = sv[(ks * 8 + tg) * 68 + nt * 8 + g];
                bfv[1] = sv[(ks * 8 + tg + 4) * 68 + nt * 8 + g];
                mma8(o[nt], af, bfv);
            }
        }
    }

    // epilogue: normalize, round to tf32 (proj GEMM consumes raw bits), store
    const float iA = 1.f / lrun[0];
    const float iB = 1.f / lrun[1];
    #pragma unroll
    for (int nt = 0; nt < 8; nt++) {
        const int col = h * HDIM + nt * 8 + tg * 2;
        *(float2*)&g_y[(size_t)(b * SEQ + rowA) * CDIM + col] = make_float2(
            __uint_as_float(f2tf(o[nt][0] * iA)), __uint_as_float(f2tf(o[nt][1] * iA)));
        *(float2*)&g_y[(size_t)(b * SEQ + rowA + 8) * CDIM + col] = make_float2(
            __uint_as_float(f2tf(o[nt][2] * iB)), __uint_as_float(f2tf(o[nt][3] * iB)));
    }
}

// ---------------------------------------------------------------------------
// Launch
// ---------------------------------------------------------------------------
extern "C" void kernel_launch(void* const* d_in, const int* in_sizes, int n_in,
                              void* d_out, int out_size)
{
    const float* x      = (const float*)d_in[0];  // [B,T,C]
    const float* W_attn = (const float*)d_in[1];  // [C,3C]
    const float* b_attn = (const float*)d_in[2];  // [3C]
    const float* W_proj = (const float*)d_in[3];  // [C,C]
    const float* b_proj = (const float*)d_in[4];  // [C]
    float* out = (float*)d_out;                   // [B,T,C]

    float *qkv, *y, *xr, *war, *wpr;
    cudaGetSymbolAddress((void**)&qkv, g_qkv);
    cudaGetSymbolAddress((void**)&y,   g_y);
    cudaGetSymbolAddress((void**)&xr,  g_xr);
    cudaGetSymbolAddress((void**)&war, g_war);
    cudaGetSymbolAddress((void**)&wpr, g_wpr);

    cudaFuncSetAttribute(attn_tc, cudaFuncAttributeMaxDynamicSharedMemorySize, ATT_SMEM);
    cudaFuncSetAttribute(gemm_tc, cudaFuncAttributeMaxDynamicSharedMemorySize, GEMM_SMEM);

    // 0) Preprocess: round x, transpose+round weights
    round_pass<<<(BT * CDIM) / (4 * 256), 256>>>(x, xr);
    wtrans<<<dim3(C3 / 32, CDIM / 32), dim3(32, 8)>>>(W_attn, war, CDIM, C3);
    wtrans<<<dim3(CDIM / 32, CDIM / 32), dim3(32, 8)>>>(W_proj, wpr, CDIM, CDIM);

    // 1) QKV projection (output rounded to tf32 for raw cp.async consumption)
    gemm_tc<<<dim3(C3 / BN, BT / BM), 256, GEMM_SMEM>>>(xr, war, b_attn, qkv,
                                                        BT, C3, CDIM, 1);
    // 2) Causal flash attention (pipelined, 128-row Q tiles)
    attn_tc<<<dim3(SEQ / 128, HEADS, BATCH), 256, ATT_SMEM>>>();

    // 3) Output projection: [8192,1024] @ [1024,1024] + b
    gemm_tc<<<dim3(CDIM / BN, BT / BM), 256, GEMM_SMEM>>>(y, wpr, b_proj, out,
                                                          BT, CDIM, CDIM, 0);
}

// round 10
// speedup vs baseline: 10.6130x; 2.0102x over previous
#include <cuda_runtime.h>
#include <cuda_fp16.h>
#include <cstdint>

// Problem constants
#define BATCH 4
#define SEQ   2048
#define CDIM  1024
#define HEADS 16
#define HDIM  64
#define BT    (BATCH * SEQ)       // 8192 rows
#define C3    (3 * CDIM)          // 3072

// Scratch in device globals (no dynamic allocation allowed)
__device__ __half g_qkv[(size_t)BT * C3];     // [B*T, 3C] fp16
__device__ __half g_y[(size_t)BT * CDIM];     // [B*T, C] attn out, fp16
__device__ __half g_xh[(size_t)BT * CDIM];    // x in fp16
__device__ __half g_wah[(size_t)C3 * CDIM];   // W_attn^T [3C][C] fp16
__device__ __half g_wph[(size_t)CDIM * CDIM]; // W_proj^T [C][C] fp16

// ---------------------------------------------------------------------------
// Helpers
// ---------------------------------------------------------------------------
__device__ __forceinline__ uint32_t smem_u32(const void* p) {
    uint32_t a;
    asm("{ .reg .u64 t; cvta.to.shared.u64 t, %1; cvt.u32.u64 %0, t; }"
        : "=r"(a) : "l"(p));
    return a;
}

__device__ __forceinline__ void mma16(float* c, const unsigned* a, const unsigned* b) {
    asm volatile(
        "mma.sync.aligned.m16n8k16.row.col.f32.f16.f16.f32 "
        "{%0,%1,%2,%3}, {%4,%5,%6,%7}, {%8,%9}, {%0,%1,%2,%3};"
        : "+f"(c[0]), "+f"(c[1]), "+f"(c[2]), "+f"(c[3])
        : "r"(a[0]), "r"(a[1]), "r"(a[2]), "r"(a[3]), "r"(b[0]), "r"(b[1]));
}

#define LDSM4(r0, r1, r2, r3, addr)                                           \
    asm volatile("ldmatrix.sync.aligned.m8n8.x4.shared.b16 {%0,%1,%2,%3}, [%4];" \
                 : "=r"(r0), "=r"(r1), "=r"(r2), "=r"(r3) : "r"(addr))

#define LDSM4T(r0, r1, r2, r3, addr)                                          \
    asm volatile("ldmatrix.sync.aligned.m8n8.x4.trans.shared.b16 {%0,%1,%2,%3}, [%4];" \
                 : "=r"(r0), "=r"(r1), "=r"(r2), "=r"(r3) : "r"(addr))

#define CP16(dst, src)                                                        \
    asm volatile("cp.async.cg.shared.global [%0], [%1], 16;"                  \
                 :: "r"(dst), "l"(src))
#define CP_COMMIT() asm volatile("cp.async.commit_group;" ::: "memory")
#define CP_WAIT(n)  asm volatile("cp.async.wait_group %0;" :: "n"(n) : "memory")

// ---------------------------------------------------------------------------
// Preprocessing: fp16 convert (and transpose for weights)
// ---------------------------------------------------------------------------
__global__ void tohalf_pass(const float* __restrict__ src, __half* __restrict__ dst) {
    const int i = blockIdx.x * blockDim.x + threadIdx.x;
    const float4 v = ((const float4*)src)[i];
    ((__half2*)dst)[2 * i + 0] = __floats2half2_rn(v.x, v.y);
    ((__half2*)dst)[2 * i + 1] = __floats2half2_rn(v.z, v.w);
}

// W[K][N] -> WT[N][K] in fp16
__global__ void wtrans(const float* __restrict__ W, __half* __restrict__ WT,
                       int K, int N) {
    __shared__ float t[32][33];
    const int n0 = blockIdx.x * 32, k0 = blockIdx.y * 32;
    const int tx = threadIdx.x, ty = threadIdx.y;
    #pragma unroll
    for (int j = 0; j < 4; j++)
        t[ty + 8 * j][tx] = W[(size_t)(k0 + ty + 8 * j) * N + n0 + tx];
    __syncthreads();
    #pragma unroll
    for (int j = 0; j < 4; j++)
        WT[(size_t)(n0 + ty + 8 * j) * K + k0 + tx] = __float2half_rn(t[tx][ty + 8 * j]);
}

// ---------------------------------------------------------------------------
// FP16 GEMM: C[M,N] = A[M,K] @ Bt[N,K]^T + bias[N]
// Block tile 128x256, K-chunk 64 (= one 128B row), 256 threads, warp 64x64.
// cp.async 4-stage pipeline, ldmatrix frags, XOR-swizzled 128B rows.
// Output either fp16 (outHalf=1) or fp32.
// ---------------------------------------------------------------------------
#define BM 128
#define BN 256
#define GSTAGE 49152           // 16KB A + 32KB B
#define GSB_OFF 16384
#define GEMM_SMEM (4 * GSTAGE) // 196608

__global__ __launch_bounds__(256, 1) void gemm_h(
    const __half* __restrict__ A, const __half* __restrict__ Bt,
    const float* __restrict__ bias, void* __restrict__ Cout,
    int M, int N, int K, int outHalf)
{
    extern __shared__ char sm[];
    const uint32_t sb = smem_u32(sm);
    const int tid  = threadIdx.x;
    const int lane = tid & 31;
    const int warp = tid >> 5;
    const int g    = lane >> 2;
    const int tg   = lane & 3;
    const int m0 = blockIdx.y * BM;
    const int n0 = blockIdx.x * BN;
    const int wm = (warp >> 2) * 64;
    const int wn = (warp & 3) * 64;

    // cp.async: thread t covers rows (t>>3)+32j, 16B chunk t&7 (8 halfs)
    const int ar  = tid >> 3;
    const int ach = tid & 7;
    const uint32_t sca = (uint32_t)((ach ^ (ar & 7)) * 16);
    const __half* aSrc = A  + (size_t)(m0 + ar) * K + ach * 8;
    const __half* bSrc = Bt + (size_t)(n0 + ar) * K + ach * 8;

    const uint32_t alr = lane & 7;
    const uint32_t aRowL = (lane & 7) + ((lane >> 3) & 1) * 8;
    const uint32_t aChL  = (lane >> 4);
    const uint32_t bRowL = (lane & 7) + ((lane >> 4) & 1) * 8;
    const uint32_t bChL  = (lane >> 3) & 1;

    float acc[4][8][4] = {};
    const int nch = K / 64;

    #pragma unroll
    for (int s = 0; s < 3; s++) {
        const uint32_t st = sb + s * GSTAGE;
        const int k0 = s * 64;
        #pragma unroll
        for (int j = 0; j < 4; j++)
            CP16(st + (uint32_t)(ar + 32 * j) * 128 + sca,
                 aSrc + k0 + (size_t)j * 32 * K);
        #pragma unroll
        for (int j = 0; j < 8; j++)
            CP16(st + GSB_OFF + (uint32_t)(ar + 32 * j) * 128 + sca,
                 bSrc + k0 + (size_t)j * 32 * K);
        CP_COMMIT();
    }

    for (int i = 0; i < nch; i++) {
        CP_WAIT(2);
        __syncthreads();

        if (i + 3 < nch) {
            const uint32_t st = sb + ((i + 3) & 3) * GSTAGE;
            const int k0 = (i + 3) * 64;
            #pragma unroll
            for (int j = 0; j < 4; j++)
                CP16(st + (uint32_t)(ar + 32 * j) * 128 + sca,
                     aSrc + k0 + (size_t)j * 32 * K);
            #pragma unroll
            for (int j = 0; j < 8; j++)
                CP16(st + GSB_OFF + (uint32_t)(ar + 32 * j) * 128 + sca,
                     bSrc + k0 + (size_t)j * 32 * K);
        }
        CP_COMMIT();

        const uint32_t stA = sb + (i & 3) * GSTAGE;
        const uint32_t stB = stA + GSB_OFF;
        #pragma unroll
        for (int ks = 0; ks < 4; ks++) {      // k16 steps: chunks 2ks, 2ks+1
            unsigned af[4][4];
            #pragma unroll
            for (int mt = 0; mt < 4; mt++) {
                const uint32_t addr = stA
                    + (uint32_t)(wm + mt * 16 + aRowL) * 128
                    + (((2u * ks + aChL) ^ alr) * 16);
                LDSM4(af[mt][0], af[mt][1], af[mt][2], af[mt][3], addr);
            }
            unsigned bf[8][2];
            #pragma unroll
            for (int p = 0; p < 4; p++) {
                const uint32_t addr = stB
                    + (uint32_t)(wn + p * 16 + bRowL) * 128
                    + (((2u * ks + bChL) ^ alr) * 16);
                LDSM4(bf[2 * p][0], bf[2 * p][1], bf[2 * p + 1][0], bf[2 * p + 1][1], addr);
            }
            #pragma unroll
            for (int mt = 0; mt < 4; mt++)
                #pragma unroll
                for (int nt = 0; nt < 8; nt++)
                    mma16(acc[mt][nt], af[mt], bf[nt]);
        }
    }

    // epilogue
    #pragma unroll
    for (int mt = 0; mt < 4; mt++) {
        const int r0 = m0 + wm + mt * 16 + g;
        #pragma unroll
        for (int nt = 0; nt < 8; nt++) {
            const int c0 = n0 + wn + nt * 8 + tg * 2;
            const float b0v = bias[c0], b1v = bias[c0 + 1];
            const float v0 = acc[mt][nt][0] + b0v, v1 = acc[mt][nt][1] + b1v;
            const float v2 = acc[mt][nt][2] + b0v, v3 = acc[mt][nt][3] + b1v;
            if (outHalf) {
                __half* Ch = (__half*)Cout;
                *(__half2*)&Ch[(size_t)r0 * N + c0] = __floats2half2_rn(v0, v1);
                *(__half2*)&Ch[(size_t)(r0 + 8) * N + c0] = __floats2half2_rn(v2, v3);
            } else {
                float* Cf = (float*)Cout;
                *(float2*)&Cf[(size_t)r0 * N + c0] = make_float2(v0, v1);
                *(float2*)&Cf[(size_t)(r0 + 8) * N + c0] = make_float2(v2, v3);
            }
        }
    }
}

// ---------------------------------------------------------------------------
// Flash attention (causal), fp16 mma.sync, cp.async pipelined.
// Block = (128-row Q tile, head, batch). 256 threads = 8 warps;
// warp w owns q rows [w*16, w*16+16). KV tiles of 64 rows, double-buffered.
// SMEM rows: 64 halfs padded to 144B (72 halfs) -> conflict-free, no swizzle.
// Layout: SP (Q staging, then P) [128][144B] | K x2 [64][144B] | V x2.
// V consumed via ldmatrix.trans (natural [j][d] layout).
// ---------------------------------------------------------------------------
#define ARS 144                         // attention smem row stride bytes
#define ATT_SP   0
#define ATT_K(s) (18432 + (s) * 9216)
#define ATT_V(s) (36864 + (s) * 9216)
#define ATT_SMEM 55296

__global__ __launch_bounds__(256) void attn_h()
{
    extern __shared__ char attsm[];
    const uint32_t base = smem_u32(attsm);

    const int tid  = threadIdx.x;
    const int lane = tid & 31;
    const int warp = tid >> 5;
    const int g    = lane >> 2;
    const int tg   = lane & 3;

    const uint32_t aRowL = (lane & 7) + ((lane >> 3) & 1) * 8;
    const uint32_t aChL  = (lane >> 4);
    const uint32_t bRowL = (lane & 7) + ((lane >> 4) & 1) * 8;
    const uint32_t bChL  = (lane >> 3) & 1;

    const int qt = (gridDim.x - 1) - blockIdx.x;   // big tiles first
    const int h  = blockIdx.y;
    const int b  = blockIdx.z;
    const __half* qkv = g_qkv + (size_t)b * SEQ * C3;

    // cp.async: 64-row tile = 64 rows x 8 chunks of 16B; 2 rows per 16 threads
    const int r8 = tid >> 3;            // 0..31
    const int ch = tid & 7;             // 0..7

    // --- Load Q (128 rows) ---
    const __half* qsrc = qkv + (size_t)(qt * 128 + r8) * C3 + h * HDIM + ch * 8;
    #pragma unroll
    for (int j = 0; j < 4; j++)
        CP16(base + ATT_SP + (uint32_t)(r8 + 32 * j) * ARS + ch * 16,
             qsrc + (size_t)(32 * j) * C3);
    CP_COMMIT();

    const __half* ksrc = qkv + (size_t)r8 * C3 + CDIM     + h * HDIM + ch * 8;
    const __half* vsrc = qkv + (size_t)r8 * C3 + 2 * CDIM + h * HDIM + ch * 8;

    // --- Prefetch KV tile 0 ---
    #pragma unroll
    for (int j = 0; j < 2; j++) {
        CP16(base + ATT_K(0) + (uint32_t)(r8 + 32 * j) * ARS + ch * 16,
             ksrc + (size_t)(32 * j) * C3);
        CP16(base + ATT_V(0) + (uint32_t)(r8 + 32 * j) * ARS + ch * 16,
             vsrc + (size_t)(32 * j) * C3);
    }
    CP_COMMIT();

    CP_WAIT(1);
    __syncthreads();

    // --- Q fragments to registers ---
    unsigned aq[4][4];
    #pragma unroll
    for (int ks = 0; ks < 4; ks++)
        LDSM4(aq[ks][0], aq[ks][1], aq[ks][2], aq[ks][3],
              base + ATT_SP + (uint32_t)(warp * 16 + aRowL) * ARS
                            + (2u * ks + aChL) * 16);

    float o[8][4] = {};
    float mrun[2] = {-1e30f, -1e30f};
    float lrun[2] = {0.f, 0.f};
    const int rowA = qt * 128 + warp * 16 + g;
    const int qmax = qt * 128 + warp * 16 + 15;

    const int ntiles = 2 * qt + 2;
    for (int i = 0; i < ntiles; i++) {
        __syncthreads();
        if (i + 1 < ntiles) {
            const uint32_t kb = base + ATT_K((i + 1) & 1);
            const uint32_t vb = base + ATT_V((i + 1) & 1);
            const size_t roff = (size_t)(i + 1) * 64 * C3;
            #pragma unroll
            for (int j = 0; j < 2; j++) {
                CP16(kb + (uint32_t)(r8 + 32 * j) * ARS + ch * 16,
                     ksrc + roff + (size_t)(32 * j) * C3);
                CP16(vb + (uint32_t)(r8 + 32 * j) * ARS + ch * 16,
                     vsrc + roff + (size_t)(32 * j) * C3);
            }
            CP_COMMIT();
            CP_WAIT(1);
        } else {
            CP_WAIT(0);
        }
        __syncthreads();

        const int jbase = i * 64;
        if (jbase > qmax) continue;

        const uint32_t kb = base + ATT_K(i & 1);
        const uint32_t vb = base + ATT_V(i & 1);

        // S = Q @ K^T  (16 x 64 per warp)
        float s[8][4] = {};
        #pragma unroll
        for (int ks = 0; ks < 4; ks++) {
            unsigned bf[8][2];
            #pragma unroll
            for (int p = 0; p < 4; p++)
                LDSM4(bf[2 * p][0], bf[2 * p][1], bf[2 * p + 1][0], bf[2 * p + 1][1],
                      kb + (uint32_t)(p * 16 + bRowL) * ARS + (2u * ks + bChL) * 16);
            #pragma unroll
            for (int nt = 0; nt < 8; nt++)
                mma16(s[nt], aq[ks], bf[nt]);
        }

        #pragma unroll
        for (int nt = 0; nt < 8; nt++) {
            s[nt][0] *= 0.125f; s[nt][1] *= 0.125f;
            s[nt][2] *= 0.125f; s[nt][3] *= 0.125f;
        }

        if (i >= 2 * qt) {
            #pragma unroll
            for (int nt = 0; nt < 8; nt++) {
                const int c = jbase + nt * 8 + tg * 2;
                if (c     > rowA)     s[nt][0] = -1e30f;
                if (c + 1 > rowA)     s[nt][1] = -1e30f;
                if (c     > rowA + 8) s[nt][2] = -1e30f;
                if (c + 1 > rowA + 8) s[nt][3] = -1e30f;
            }
        }

        // online softmax
        float mA = -1e30f, mB = -1e30f;
        #pragma unroll
        for (int nt = 0; nt < 8; nt++) {
            mA = fmaxf(mA, fmaxf(s[nt][0], s[nt][1]));
            mB = fmaxf(mB, fmaxf(s[nt][2], s[nt][3]));
        }
        mA = fmaxf(mA, __shfl_xor_sync(0xffffffffu, mA, 1));
        mA = fmaxf(mA, __shfl_xor_sync(0xffffffffu, mA, 2));
        mB = fmaxf(mB, __shfl_xor_sync(0xffffffffu, mB, 1));
        mB = fmaxf(mB, __shfl_xor_sync(0xffffffffu, mB, 2));

        const float mnA = fmaxf(mrun[0], mA);
        const float mnB = fmaxf(mrun[1], mB);
        const float cA  = __expf(mrun[0] - mnA);
        const float cB  = __expf(mrun[1] - mnB);

        float sumA = 0.f, sumB = 0.f;
        __half* sph = (__half*)(attsm + ATT_SP);
        #pragma unroll
        for (int nt = 0; nt < 8; nt++) {
            const float p0 = __expf(s[nt][0] - mnA);
            const float p1 = __expf(s[nt][1] - mnA);
            const float p2 = __expf(s[nt][2] - mnB);
            const float p3 = __expf(s[nt][3] - mnB);
            sumA += p0 + p1;
            sumB += p2 + p3;
            const int col = nt * 8 + tg * 2;
            *(__half2*)&sph[(warp * 16 + g) * 72 + col]     = __floats2half2_rn(p0, p1);
            *(__half2*)&sph[(warp * 16 + g + 8) * 72 + col] = __floats2half2_rn(p2, p3);
            o[nt][0] *= cA; o[nt][1] *= cA;
            o[nt][2] *= cB; o[nt][3] *= cB;
        }
        sumA += __shfl_xor_sync(0xffffffffu, sumA, 1);
        sumA += __shfl_xor_sync(0xffffffffu, sumA, 2);
        sumB += __shfl_xor_sync(0xffffffffu, sumB, 1);
        sumB += __shfl_xor_sync(0xffffffffu, sumB, 2);
        lrun[0] = lrun[0] * cA + sumA;
        lrun[1] = lrun[1] * cB + sumB;
        mrun[0] = mnA;
        mrun[1] = mnB;

        __syncwarp();   // P STS -> LDSM (warp-private rows)

        // O += P @ V  (B frags via ldmatrix.trans from natural [j][d] V)
        #pragma unroll
        for (int ks = 0; ks < 4; ks++) {   // k = j 16ks..16ks+16
            unsigned af[4];
            LDSM4(af[0], af[1], af[2], af[3],
                  base + ATT_SP + (uint32_t)(warp * 16 + aRowL) * ARS
                                + (2u * ks + aChL) * 16);
            unsigned bf[8][2];
            #pragma unroll
            for (int p = 0; p < 4; p++)
                LDSM4T(bf[2 * p][0], bf[2 * p][1], bf[2 * p + 1][0], bf[2 * p + 1][1],
                       vb + (uint32_t)(16 * ks + aRowL) * ARS + (2u * p + aChL) * 16);
            #pragma unroll
            for (int nt = 0; nt < 8; nt++)
                mma16(o[nt], af, bf[nt]);
        }
    }

    // epilogue: normalize, store fp16 y
    const float iA = 1.f / lrun[0];
    const float iB = 1.f / lrun[1];
    #pragma unroll
    for (int nt = 0; nt < 8; nt++) {
        const int col = h * HDIM + nt * 8 + tg * 2;
        *(__half2*)&g_y[(size_t)(b * SEQ + rowA) * CDIM + col] =
            __floats2half2_rn(o[nt][0] * iA, o[nt][1] * iA);
        *(__half2*)&g_y[(size_t)(b * SEQ + rowA + 8) * CDIM + col] =
            __floats2half2_rn(o[nt][2] * iB, o[nt][3] * iB);
    }
}

// ---------------------------------------------------------------------------
// Launch
// ---------------------------------------------------------------------------
extern "C" void kernel_launch(void* const* d_in, const int* in_sizes, int n_in,
                              void* d_out, int out_size)
{
    const float* x      = (const float*)d_in[0];  // [B,T,C]
    const float* W_attn = (const float*)d_in[1];  // [C,3C]
    const float* b_attn = (const float*)d_in[2];  // [3C]
    const float* W_proj = (const float*)d_in[3];  // [C,C]
    const float* b_proj = (const float*)d_in[4];  // [C]
    float* out = (float*)d_out;                   // [B,T,C]

    __half *qkv, *y, *xh, *wah, *wph;
    cudaGetSymbolAddress((void**)&qkv, g_qkv);
    cudaGetSymbolAddress((void**)&y,   g_y);
    cudaGetSymbolAddress((void**)&xh,  g_xh);
    cudaGetSymbolAddress((void**)&wah, g_wah);
    cudaGetSymbolAddress((void**)&wph, g_wph);

    cudaFuncSetAttribute(attn_h, cudaFuncAttributeMaxDynamicSharedMemorySize, ATT_SMEM);
    cudaFuncSetAttribute(gemm_h, cudaFuncAttributeMaxDynamicSharedMemorySize, GEMM_SMEM);

    // 0) Preprocess: convert x, transpose+convert weights
    tohalf_pass<<<(BT * CDIM) / (4 * 256), 256>>>(x, xh);
    wtrans<<<dim3(C3 / 32, CDIM / 32), dim3(32, 8)>>>(W_attn, wah, CDIM, C3);
    wtrans<<<dim3(CDIM / 32, CDIM / 32), dim3(32, 8)>>>(W_proj, wph, CDIM, CDIM);

    // 1) QKV projection -> fp16 qkv
    gemm_h<<<dim3(C3 / BN, BT / BM), 256, GEMM_SMEM>>>(xh, wah, b_attn, qkv,
                                                       BT, C3, CDIM, 1);
    // 2) Causal flash attention -> fp16 y
    attn_h<<<dim3(SEQ / 128, HEADS, BATCH), 256, ATT_SMEM>>>();

    // 3) Output projection -> fp32 out
    gemm_h<<<dim3(CDIM / BN, BT / BM), 256, GEMM_SMEM>>>(y, wph, b_proj, out,
                                                         BT, CDIM, CDIM, 0);
}